// round 1
// baseline (speedup 1.0000x reference)
#include <cuda_runtime.h>
#include <math.h>

// Problem constants (fixed shapes)
#define B_DIM   32
#define C_DIM   256
#define HW_DIM  1024           // 32*32
#define N_TOK   32768          // B*H*W
#define K_CODES 1024
#define Z_ELEMS 8388608        // 32*256*32*32
#define BETA_F  0.25f

// Tiling for the GEMM-argmin
#define MT      64             // tokens per block
#define NT      64             // codes per chunk
#define CHUNKS  (K_CODES / NT) // 16
#define RPAD    260            // padded row length (floats), 65 float4
#define RPAD4   65

// Gather/loss kernel
#define GL_BLOCKS 4096
#define GL_TPB    256
#define GL_PER_T  8            // 4096*256*8 = 8388608

// Scratch (no allocations allowed)
static __device__ int   g_idx[N_TOK];
static __device__ int   g_counts[K_CODES];
static __device__ float g_norms[K_CODES];
static __device__ float g_partials[GL_BLOCKS];

// ---------------------------------------------------------------------------
// 0) zero histogram
__global__ void init_kernel() {
    g_counts[threadIdx.x] = 0;
}

// ---------------------------------------------------------------------------
// 1) codebook row norms: one warp per code
__global__ void norms_kernel(const float* __restrict__ cb) {
    int code = blockIdx.x * 8 + (threadIdx.x >> 5);
    int lane = threadIdx.x & 31;
    const float* row = cb + code * C_DIM;
    float s = 0.f;
    #pragma unroll
    for (int c = lane; c < C_DIM; c += 32) {
        float v = row[c];
        s += v * v;
    }
    #pragma unroll
    for (int off = 16; off > 0; off >>= 1)
        s += __shfl_down_sync(0xffffffffu, s, off);
    if (lane == 0) g_norms[code] = s;
}

// ---------------------------------------------------------------------------
// 2) fp32 GEMM-argmin: block = 64 tokens x all 1024 codes
//    threads: 256 = (tx:16, ty:16); each thread: 4 tokens x 4 codes reg tile
__global__ __launch_bounds__(256, 1)
void argmin_kernel(const float* __restrict__ z, const float* __restrict__ cb) {
    extern __shared__ float4 smem4[];
    float4* zs4 = smem4;                    // 64 x 65 float4
    float4* es4 = smem4 + MT * RPAD4;       // 64 x 65 float4
    float*  candv = (float*)(es4 + NT * RPAD4);   // 64 x 16
    int*    candi = (int*)(candv + MT * 16);      // 64 x 16

    const int tid = threadIdx.x;
    const int tx = tid & 15;
    const int ty = tid >> 4;

    const int n0  = blockIdx.x * MT;
    const int b   = n0 >> 10;
    const int hw0 = n0 & 1023;
    const float* zb = z + (size_t)b * (C_DIM * HW_DIM) + hw0;

    // Stage z tile: zs[t][c], coalesced over t (gmem contiguous in hw)
    {
        float* zs = (float*)zs4;
        #pragma unroll
        for (int i = tid; i < MT * C_DIM; i += 256) {
            int t = i & (MT - 1);
            int c = i >> 6;
            zs[t * RPAD + c] = zb[c * HW_DIM + t];
        }
    }

    float bestv[4];
    int   besti[4];
    #pragma unroll
    for (int i = 0; i < 4; i++) { bestv[i] = 3.4e38f; besti[i] = 0; }

    const float4* cbf4 = (const float4*)cb;    // row stride 64 float4
    const float4* za   = zs4 + (ty * 4) * RPAD4;
    const float4* eb0  = es4 + (tx * 4) * RPAD4;

    for (int ch = 0; ch < CHUNKS; ch++) {
        const int k0 = ch * NT;
        __syncthreads();   // protect es from previous chunk's readers
        // Stage codebook chunk: es[j][c], coalesced float4 over c
        #pragma unroll
        for (int it = 0; it < 16; it++) {
            int i2 = tid + it * 256;
            int j  = i2 >> 6;
            int c4 = i2 & 63;
            es4[j * RPAD4 + c4] = cbf4[(size_t)(k0 + j) * 64 + c4];
        }
        __syncthreads();

        float acc[4][4];
        #pragma unroll
        for (int i = 0; i < 4; i++)
            #pragma unroll
            for (int j = 0; j < 4; j++) acc[i][j] = 0.f;

        #pragma unroll 4
        for (int c4 = 0; c4 < 64; c4++) {
            float4 a[4], bb[4];
            #pragma unroll
            for (int i = 0; i < 4; i++) a[i]  = za[i * RPAD4 + c4];
            #pragma unroll
            for (int j = 0; j < 4; j++) bb[j] = eb0[j * RPAD4 + c4];
            #pragma unroll
            for (int i = 0; i < 4; i++)
                #pragma unroll
                for (int j = 0; j < 4; j++) {
                    acc[i][j] += a[i].x * bb[j].x;
                    acc[i][j] += a[i].y * bb[j].y;
                    acc[i][j] += a[i].z * bb[j].z;
                    acc[i][j] += a[i].w * bb[j].w;
                }
        }

        // distance = |e|^2 - 2 z.e  (per-token |z|^2 dropped: constant)
        #pragma unroll
        for (int j = 0; j < 4; j++) {
            int k = k0 + tx * 4 + j;
            float nk = g_norms[k];
            #pragma unroll
            for (int i = 0; i < 4; i++) {
                float d = nk - 2.f * acc[i][j];
                if (d < bestv[i]) { bestv[i] = d; besti[i] = k; }
            }
        }
    }

    // Cross-tx argmin reduction (codes monotone in tx -> strict < keeps first)
    #pragma unroll
    for (int i = 0; i < 4; i++) {
        int row = ty * 4 + i;
        candv[row * 16 + tx] = bestv[i];
        candi[row * 16 + tx] = besti[i];
    }
    __syncthreads();
    if (tid < MT) {
        float bv = candv[tid * 16];
        int   bi = candi[tid * 16];
        #pragma unroll
        for (int t = 1; t < 16; t++) {
            float v = candv[tid * 16 + t];
            int   k = candi[tid * 16 + t];
            if (v < bv || (v == bv && k < bi)) { bv = v; bi = k; }
        }
        g_idx[n0 + tid] = bi;
        atomicAdd(&g_counts[bi], 1);   // int atomics: order-independent
    }
}

// ---------------------------------------------------------------------------
// 3) gather z_q into [B,C,H,W] output + per-block sum of (z_q - z)^2
__global__ __launch_bounds__(GL_TPB)
void gather_loss_kernel(const float* __restrict__ z,
                        const float* __restrict__ cb,
                        float* __restrict__ out) {
    __shared__ float red[GL_TPB];
    const int tid = threadIdx.x;
    float s = 0.f;
    size_t base = (size_t)blockIdx.x * (GL_TPB * GL_PER_T);
    #pragma unroll
    for (int r = 0; r < GL_PER_T; r++) {
        size_t e = base + r * GL_TPB + tid;
        int b  = (int)(e >> 18);        // / (256*1024)
        int c  = (int)((e >> 10) & 255);
        int hw = (int)(e & 1023);
        int n  = (b << 10) + hw;
        int k  = g_idx[n];
        float q = cb[(size_t)k * C_DIM + c];
        float d = q - z[e];
        s += d * d;
        out[e] = q;
    }
    red[tid] = s;
    __syncthreads();
    for (int off = GL_TPB / 2; off > 0; off >>= 1) {
        if (tid < off) red[tid] += red[tid + off];
        __syncthreads();
    }
    if (tid == 0) g_partials[blockIdx.x] = red[0];
}

// ---------------------------------------------------------------------------
// 4) finalize: deterministic fixed-tree reduction of loss + entropy
__global__ void finalize_kernel(float* __restrict__ out, int out_size) {
    __shared__ float s1[1024];
    __shared__ float s2[1024];
    const int tid = threadIdx.x;
    float ls = g_partials[tid] + g_partials[tid + 1024]
             + g_partials[tid + 2048] + g_partials[tid + 3072];
    float p  = (float)g_counts[tid] * (1.0f / (float)N_TOK);
    float pc = fmaxf(p, 1e-10f);
    float en = pc * logf(pc);
    s1[tid] = ls;
    s2[tid] = en;
    __syncthreads();
    for (int off = 512; off > 0; off >>= 1) {
        if (tid < off) { s1[tid] += s1[tid + off]; s2[tid] += s2[tid + off]; }
        __syncthreads();
    }
    if (tid == 0) {
        float mse = s1[0] * (1.0f / (float)Z_ELEMS);
        float vq_loss = mse * (1.0f + BETA_F);
        float perp = expf(-s2[0]);
        if (out_size >= Z_ELEMS + 1) out[Z_ELEMS]     = vq_loss;
        if (out_size >= Z_ELEMS + 2) out[Z_ELEMS + 1] = perp;
    }
}

// ---------------------------------------------------------------------------
extern "C" void kernel_launch(void* const* d_in, const int* in_sizes, int n_in,
                              void* d_out, int out_size) {
    const float* z  = (const float*)d_in[0];
    const float* cb = (const float*)d_in[1];
    float* out = (float*)d_out;

    const size_t ARG_SMEM = (size_t)(MT * RPAD4 + NT * RPAD4) * sizeof(float4)
                          + (size_t)MT * 16 * (sizeof(float) + sizeof(int));
    cudaFuncSetAttribute(argmin_kernel,
                         cudaFuncAttributeMaxDynamicSharedMemorySize,
                         (int)ARG_SMEM);

    init_kernel<<<1, K_CODES>>>();
    norms_kernel<<<K_CODES / 8, 256>>>(cb);
    argmin_kernel<<<N_TOK / MT, 256, ARG_SMEM>>>(z, cb);
    gather_loss_kernel<<<GL_BLOCKS, GL_TPB>>>(z, cb, out);
    finalize_kernel<<<1, 1024>>>(out, out_size);
}

// round 2
// speedup vs baseline: 3.3248x; 3.3248x over previous
#include <cuda_runtime.h>
#include <math.h>
#include <stdint.h>

// Shapes (fixed)
#define B_DIM   32
#define C_DIM   256
#define HW_DIM  1024
#define N_TOK   32768
#define K_CODES 1024
#define Z_ELEMS 8388608
#define BETA_F  0.25f

// argmin-MMA tiling
#define MT      128            // tokens per CTA
#define NCH     64             // codes per chunk
#define CHUNKS  (K_CODES / NCH)
#define RPAD    260            // padded row stride in floats (ldmatrix-clean)

// gather
#define GL_BLOCKS (N_TOK / 256)  // 128

static __device__ int   g_idx[N_TOK];
static __device__ int   g_counts[K_CODES];
static __device__ float g_norms[K_CODES];
static __device__ float g_partials[GL_BLOCKS];

// ---------------------------------------------------------------------------
__global__ void init_kernel() { g_counts[threadIdx.x] = 0; }

// ---------------------------------------------------------------------------
__global__ void norms_kernel(const float* __restrict__ cb) {
    int code = blockIdx.x * 8 + (threadIdx.x >> 5);
    int lane = threadIdx.x & 31;
    const float* row = cb + code * C_DIM;
    float s = 0.f;
    #pragma unroll
    for (int c = lane; c < C_DIM; c += 32) { float v = row[c]; s += v * v; }
    #pragma unroll
    for (int off = 16; off > 0; off >>= 1)
        s += __shfl_down_sync(0xffffffffu, s, off);
    if (lane == 0) g_norms[code] = s;
}

// ---------------------------------------------------------------------------
// helpers
__device__ __forceinline__ uint32_t f2tf32(float a) {
    uint32_t r;
    asm("cvt.rna.tf32.f32 %0, %1;" : "=r"(r) : "f"(a));
    return r;
}
__device__ __forceinline__ void split_tf32(float a, uint32_t& hi, uint32_t& lo) {
    hi = f2tf32(a);
    float hif = __uint_as_float(hi);
    lo = f2tf32(a - hif);
}
__device__ __forceinline__ void ldsm4(uint32_t addr, uint32_t r[4]) {
    asm volatile("ldmatrix.sync.aligned.m8n8.x4.shared.b16 {%0,%1,%2,%3}, [%4];"
                 : "=r"(r[0]), "=r"(r[1]), "=r"(r[2]), "=r"(r[3]) : "r"(addr));
}
__device__ __forceinline__ void mma_tf32(float c[4], const uint32_t a[4],
                                         uint32_t b0, uint32_t b1) {
    asm volatile(
        "mma.sync.aligned.m16n8k8.row.col.f32.tf32.tf32.f32 "
        "{%0,%1,%2,%3}, {%4,%5,%6,%7}, {%8,%9}, {%0,%1,%2,%3};"
        : "+f"(c[0]), "+f"(c[1]), "+f"(c[2]), "+f"(c[3])
        : "r"(a[0]), "r"(a[1]), "r"(a[2]), "r"(a[3]), "r"(b0), "r"(b1));
}

// ---------------------------------------------------------------------------
// 3xTF32 tensor-core GEMM-argmin.
// CTA: 128 tokens x all 1024 codes (16 chunks of 64).
// 8 warps = 4 token-groups x 2 code-groups; warp tile = 32 tok x 32 codes.
__global__ __launch_bounds__(256, 1)
void argmin_kernel(const float* __restrict__ z, const float* __restrict__ cb) {
    extern __shared__ float smem[];
    float* As = smem;                          // [128][260]
    float* Bs = smem + MT * RPAD;              // [64][260]
    float* ns = Bs + NCH * RPAD;               // [64]
    float* candv = ns + 64;                    // [128][2]
    int*   candi = (int*)(candv + MT * 2);     // [128][2]

    const int tid  = threadIdx.x;
    const int warp = tid >> 5;
    const int lane = tid & 31;
    const int tg   = warp & 3;     // token group (32 tokens)
    const int cg   = warp >> 2;    // code group (32 codes of the 64-chunk)
    const int g    = lane >> 2;
    const int t    = lane & 3;

    const int n0  = blockIdx.x * MT;
    const int b   = n0 >> 10;
    const int hw0 = n0 & 1023;
    const float* zb = z + (size_t)b * (C_DIM * HW_DIM) + hw0;

    // Stage A (128 tokens x 256 c), coalesced over tokens
    #pragma unroll
    for (int it = 0; it < (MT * C_DIM) / 256; it++) {
        int i = it * 256 + tid;
        int tk = i & (MT - 1);
        int c  = i >> 7;
        As[tk * RPAD + c] = zb[c * HW_DIM + tk];
    }

    // ldmatrix per-lane base address (A fragment as 16x16 b16)
    uint32_t as_base;
    asm("{ .reg .u64 T; cvta.to.shared.u64 T, %1; cvt.u32.u64 %0, T; }"
        : "=r"(as_base) : "l"(As));
    const int arow = lane & 15;
    const int aboff = (lane >> 4) * 16;
    const uint32_t a_base = as_base + (uint32_t)((tg * 32 + arow) * RPAD * 4) + aboff;

    float bestv[4];
    int   besti[4];
    #pragma unroll
    for (int s = 0; s < 4; s++) { bestv[s] = 3.4e38f; besti[s] = 0; }

    const float4* cb4 = (const float4*)cb;

    for (int ch = 0; ch < CHUNKS; ch++) {
        const int k0 = ch * NCH;
        __syncthreads();
        // Stage B chunk (64 codes x 256 c) via float4 + chunk norms
        #pragma unroll
        for (int it = 0; it < (NCH * 64) / 256; it++) {
            int i  = it * 256 + tid;
            int c4 = i & 63;
            int n  = i >> 6;
            float4 v = cb4[(size_t)(k0 + n) * 64 + c4];
            float* d = Bs + n * RPAD + c4 * 4;
            d[0] = v.x; d[1] = v.y; d[2] = v.z; d[3] = v.w;
        }
        if (tid < NCH) ns[tid] = g_norms[k0 + tid];
        __syncthreads();

        float acc[2][4][4];
        #pragma unroll
        for (int mt = 0; mt < 2; mt++)
            #pragma unroll
            for (int nb = 0; nb < 4; nb++)
                #pragma unroll
                for (int q = 0; q < 4; q++) acc[mt][nb][q] = 0.f;

        #pragma unroll 4
        for (int ks = 0; ks < 32; ks++) {
            uint32_t ahi[2][4], alo[2][4];
            #pragma unroll
            for (int mt = 0; mt < 2; mt++) {
                uint32_t r[4];
                ldsm4(a_base + (uint32_t)(mt * 16 * RPAD * 4 + ks * 32), r);
                #pragma unroll
                for (int q = 0; q < 4; q++)
                    split_tf32(__uint_as_float(r[q]), ahi[mt][q], alo[mt][q]);
            }
            #pragma unroll
            for (int nb = 0; nb < 4; nb++) {
                const float* bp = Bs + (cg * 32 + nb * 8 + g) * RPAD + ks * 8 + t;
                float b0f = bp[0];
                float b1f = bp[4];
                uint32_t bh0, bl0, bh1, bl1;
                split_tf32(b0f, bh0, bl0);
                split_tf32(b1f, bh1, bl1);
                #pragma unroll
                for (int mt = 0; mt < 2; mt++) {
                    mma_tf32(acc[mt][nb], ahi[mt], bh0, bh1);
                    mma_tf32(acc[mt][nb], alo[mt], bh0, bh1);
                    mma_tf32(acc[mt][nb], ahi[mt], bl0, bl1);
                }
            }
        }

        // epilogue: dist = |e|^2 - 2 z.e ; running min per (mt, row-half)
        #pragma unroll
        for (int nb = 0; nb < 4; nb++) {
            int cl = cg * 32 + nb * 8 + 2 * t;   // local code of col0
            float nk0 = ns[cl];
            float nk1 = ns[cl + 1];
            int code0 = k0 + cl;
            #pragma unroll
            for (int mt = 0; mt < 2; mt++) {
                float d00 = nk0 - 2.f * acc[mt][nb][0];
                float d01 = nk1 - 2.f * acc[mt][nb][1];
                float d10 = nk0 - 2.f * acc[mt][nb][2];
                float d11 = nk1 - 2.f * acc[mt][nb][3];
                int s0 = mt * 2, s1 = mt * 2 + 1;
                if (d00 < bestv[s0]) { bestv[s0] = d00; besti[s0] = code0; }
                if (d01 < bestv[s0]) { bestv[s0] = d01; besti[s0] = code0 + 1; }
                if (d10 < bestv[s1]) { bestv[s1] = d10; besti[s1] = code0; }
                if (d11 < bestv[s1]) { bestv[s1] = d11; besti[s1] = code0 + 1; }
            }
        }
    }

    // reduce across the 4 lanes sharing a row (lanes 4g..4g+3)
    #pragma unroll
    for (int s = 0; s < 4; s++) {
        #pragma unroll
        for (int m = 1; m <= 2; m <<= 1) {
            float v2 = __shfl_xor_sync(0xffffffffu, bestv[s], m);
            int   i2 = __shfl_xor_sync(0xffffffffu, besti[s], m);
            if (v2 < bestv[s] || (v2 == bestv[s] && i2 < besti[s])) {
                bestv[s] = v2; besti[s] = i2;
            }
        }
    }
    if (t == 0) {
        #pragma unroll
        for (int s = 0; s < 4; s++) {
            int mt = s >> 1, h = s & 1;
            int tok = tg * 32 + mt * 16 + h * 8 + g;
            candv[tok * 2 + cg] = bestv[s];
            candi[tok * 2 + cg] = besti[s];
        }
    }
    __syncthreads();
    if (tid < MT) {
        float v0 = candv[tid * 2],     v1 = candv[tid * 2 + 1];
        int   i0 = candi[tid * 2],     i1 = candi[tid * 2 + 1];
        int bi; 
        if (v1 < v0 || (v1 == v0 && i1 < i0)) bi = i1; else bi = i0;
        g_idx[n0 + tid] = bi;
        atomicAdd(&g_counts[bi], 1);
    }
}

// ---------------------------------------------------------------------------
// thread-per-token gather: sequential cb row reads, coalesced z/out
__global__ __launch_bounds__(256)
void gather_loss_kernel(const float* __restrict__ z,
                        const float* __restrict__ cb,
                        float* __restrict__ out) {
    __shared__ float red[256];
    const int tid = threadIdx.x;
    const int n = blockIdx.x * 256 + tid;
    const int b = n >> 10;
    const int hw = n & 1023;
    const int k = g_idx[n];
    const float4* c4p = (const float4*)(cb + (size_t)k * C_DIM);
    const float* zp = z + (size_t)b * (C_DIM * HW_DIM) + hw;
    float* op = out + (size_t)b * (C_DIM * HW_DIM) + hw;
    float s = 0.f;
    #pragma unroll 8
    for (int c4 = 0; c4 < 64; c4++) {
        float4 e = c4p[c4];
        int c = c4 * 4;
        float z0 = zp[(c + 0) * HW_DIM];
        float z1 = zp[(c + 1) * HW_DIM];
        float z2 = zp[(c + 2) * HW_DIM];
        float z3 = zp[(c + 3) * HW_DIM];
        float d0 = e.x - z0, d1 = e.y - z1, d2 = e.z - z2, d3 = e.w - z3;
        s += d0 * d0 + d1 * d1 + d2 * d2 + d3 * d3;
        op[(c + 0) * HW_DIM] = e.x;
        op[(c + 1) * HW_DIM] = e.y;
        op[(c + 2) * HW_DIM] = e.z;
        op[(c + 3) * HW_DIM] = e.w;
    }
    red[tid] = s;
    __syncthreads();
    for (int off = 128; off > 0; off >>= 1) {
        if (tid < off) red[tid] += red[tid + off];
        __syncthreads();
    }
    if (tid == 0) g_partials[blockIdx.x] = red[0];
}

// ---------------------------------------------------------------------------
__global__ void finalize_kernel(float* __restrict__ out, int out_size) {
    __shared__ float s1[1024];
    __shared__ float s2[1024];
    const int tid = threadIdx.x;
    float ls = (tid < GL_BLOCKS) ? g_partials[tid] : 0.f;
    float p  = (float)g_counts[tid] * (1.0f / (float)N_TOK);
    float pc = fmaxf(p, 1e-10f);
    float en = pc * logf(pc);
    s1[tid] = ls;
    s2[tid] = en;
    __syncthreads();
    for (int off = 512; off > 0; off >>= 1) {
        if (tid < off) { s1[tid] += s1[tid + off]; s2[tid] += s2[tid + off]; }
        __syncthreads();
    }
    if (tid == 0) {
        float mse = s1[0] * (1.0f / (float)Z_ELEMS);
        float vq_loss = mse * (1.0f + BETA_F);
        float perp = expf(-s2[0]);
        if (out_size >= Z_ELEMS + 1) out[Z_ELEMS]     = vq_loss;
        if (out_size >= Z_ELEMS + 2) out[Z_ELEMS + 1] = perp;
    }
}

// ---------------------------------------------------------------------------
extern "C" void kernel_launch(void* const* d_in, const int* in_sizes, int n_in,
                              void* d_out, int out_size) {
    const float* z  = (const float*)d_in[0];
    const float* cb = (const float*)d_in[1];
    float* out = (float*)d_out;

    const size_t ARG_SMEM = (size_t)(MT * RPAD + NCH * RPAD + 64 + MT * 2) * 4
                          + (size_t)MT * 2 * 4;
    cudaFuncSetAttribute(argmin_kernel,
                         cudaFuncAttributeMaxDynamicSharedMemorySize,
                         (int)ARG_SMEM);

    init_kernel<<<1, K_CODES>>>();
    norms_kernel<<<K_CODES / 8, 256>>>(cb);
    argmin_kernel<<<N_TOK / MT, 256, ARG_SMEM>>>(z, cb);
    gather_loss_kernel<<<GL_BLOCKS, 256>>>(z, cb, out);
    finalize_kernel<<<1, 1024>>>(out, out_size);
}

// round 4
// speedup vs baseline: 7.0474x; 2.1196x over previous
#include <cuda_runtime.h>
#include <cuda_fp16.h>
#include <math.h>
#include <stdint.h>

// Shapes (fixed)
#define HW_DIM  1024
#define C_DIM   256
#define N_TOK   32768
#define K_CODES 1024
#define Z_ELEMS 8388608
#define BETA_F  0.25f

// tiling
#define MT      128            // tokens per CTA
#define NCH     64             // codes per chunk
#define CHUNKS  (K_CODES / NCH)
#define KSTEPS  (C_DIM / 16)   // 16 k-steps of k16

// fp16 split scale
#define LO_S    2048.0f
#define LO_IS   4.8828125e-4f  // 1/2048

// smem layout (bytes). fp16 rows padded to 264 halves = 528 B (ldsm conflict-free)
#define ROWB    528
#define AH_OFF  0
#define AL_OFF  67584           // 128*528
#define BH_OFF  135168
#define BL_OFF  168960          // + 64*528
#define NS_OFF  202752          // 64 floats
#define CV_OFF  203008          // 128*2 floats
#define CI_OFF  204032          // 128*2 ints
#define SMEM_TOTAL 205056

#define GL_BLOCKS 512

static __device__ int   g_idx[N_TOK];
static __device__ int   g_counts[K_CODES];
static __device__ float g_norms[K_CODES];
static __device__ float g_partials[GL_BLOCKS];

// ---------------------------------------------------------------------------
__global__ void init_kernel() { g_counts[threadIdx.x] = 0; }

__global__ void norms_kernel(const float* __restrict__ cb) {
    int code = blockIdx.x * 8 + (threadIdx.x >> 5);
    int lane = threadIdx.x & 31;
    const float* row = cb + code * C_DIM;
    float s = 0.f;
    #pragma unroll
    for (int c = lane; c < C_DIM; c += 32) { float v = row[c]; s += v * v; }
    #pragma unroll
    for (int off = 16; off > 0; off >>= 1)
        s += __shfl_down_sync(0xffffffffu, s, off);
    if (lane == 0) g_norms[code] = s;
}

// ---------------------------------------------------------------------------
__device__ __forceinline__ uint32_t smem_u32(const void* p) {
    uint32_t a;
    asm("{ .reg .u64 T; cvta.to.shared.u64 T, %1; cvt.u32.u64 %0, T; }"
        : "=r"(a) : "l"(p));
    return a;
}
__device__ __forceinline__ void ldsm4(uint32_t addr, uint32_t r[4]) {
    asm volatile("ldmatrix.sync.aligned.m8n8.x4.shared.b16 {%0,%1,%2,%3}, [%4];"
                 : "=r"(r[0]), "=r"(r[1]), "=r"(r[2]), "=r"(r[3]) : "r"(addr));
}
__device__ __forceinline__ void ldsm2(uint32_t addr, uint32_t r[2]) {
    asm volatile("ldmatrix.sync.aligned.m8n8.x2.shared.b16 {%0,%1}, [%2];"
                 : "=r"(r[0]), "=r"(r[1]) : "r"(addr));
}
__device__ __forceinline__ void mma_f16(float c[4], const uint32_t a[4],
                                        uint32_t b0, uint32_t b1) {
    asm volatile(
        "mma.sync.aligned.m16n8k16.row.col.f32.f16.f16.f32 "
        "{%0,%1,%2,%3}, {%4,%5,%6,%7}, {%8,%9}, {%0,%1,%2,%3};"
        : "+f"(c[0]), "+f"(c[1]), "+f"(c[2]), "+f"(c[3])
        : "r"(a[0]), "r"(a[1]), "r"(a[2]), "r"(a[3]), "r"(b0), "r"(b1));
}
__device__ __forceinline__ void split16(float a, __half& hi, __half& lo) {
    hi = __float2half_rn(a);
    lo = __float2half_rn((a - __half2float(hi)) * LO_S);
}

// ---------------------------------------------------------------------------
// split-fp16 tensor-core GEMM-argmin.
// CTA: 128 tokens x all 1024 codes (16 chunks of 64).
// 8 warps = 4 token-groups x 2 code-groups; warp tile = 32 tok x 32 codes.
__global__ __launch_bounds__(256, 1)
void argmin_kernel(const float* __restrict__ z, const float* __restrict__ cb) {
    extern __shared__ char smem[];
    const uint32_t sb = smem_u32(smem);
    float* ns    = (float*)(smem + NS_OFF);
    float* candv = (float*)(smem + CV_OFF);
    int*   candi = (int*)(smem + CI_OFF);

    const int tid  = threadIdx.x;
    const int warp = tid >> 5;
    const int lane = tid & 31;
    const int tg   = warp & 3;
    const int cg   = warp >> 2;
    const int g    = lane >> 2;
    const int t    = lane & 3;
    const int l15  = lane & 15;

    const int n0  = blockIdx.x * MT;
    const int b   = n0 >> 10;
    const int hw0 = n0 & 1023;
    const float* zb = z + (size_t)b * (C_DIM * HW_DIM) + hw0;
    const float4* cb4 = (const float4*)cb;

    // stage A (128 tok x 256 c) as fp16 hi/lo, coalesced over tokens
    for (int it = 0; it < 128; it++) {
        int i  = it * 256 + tid;
        int tk = i & 127;
        int c  = i >> 7;
        float a = zb[(size_t)c * HW_DIM + tk];
        __half hi, lo;
        split16(a, hi, lo);
        *(__half*)(smem + AH_OFF + tk * ROWB + c * 2) = hi;
        *(__half*)(smem + AL_OFF + tk * ROWB + c * 2) = lo;
    }

    const uint32_t aH  = sb + AH_OFF + (uint32_t)((tg * 32 + l15) * ROWB + (lane >> 4) * 16);
    const uint32_t aL  = aH + (uint32_t)(AL_OFF - AH_OFF);
    const uint32_t bHb = sb + BH_OFF + (uint32_t)((cg * 32 + (l15 & 7)) * ROWB + (l15 >> 3) * 16);
    const uint32_t bLb = bHb + (uint32_t)(BL_OFF - BH_OFF);

    float bestv4[4];
    int   besti4[4];
    #pragma unroll
    for (int s = 0; s < 4; s++) { bestv4[s] = 3.4e38f; besti4[s] = 0; }

    for (int ch = 0; ch < CHUNKS; ch++) {
        const int k0c = ch * NCH;
        __syncthreads();   // protect B from previous chunk's readers
        // stage B chunk (64 codes x 256 c) fp16 hi/lo
        #pragma unroll
        for (int it = 0; it < 16; it++) {
            int i    = it * 256 + tid;
            int code = i >> 6;
            int j4   = i & 63;
            float4 v = cb4[(size_t)(k0c + code) * 64 + j4];
            __half h0, l0, h1, l1, h2, l2, h3, l3;
            split16(v.x, h0, l0); split16(v.y, h1, l1);
            split16(v.z, h2, l2); split16(v.w, h3, l3);
            __half2 hA = __halves2half2(h0, h1), hB = __halves2half2(h2, h3);
            __half2 lA = __halves2half2(l0, l1), lB = __halves2half2(l2, l3);
            uint32_t off = (uint32_t)(code * ROWB + j4 * 8);
            *(uint2*)(smem + BH_OFF + off) = make_uint2(*(uint32_t*)&hA, *(uint32_t*)&hB);
            *(uint2*)(smem + BL_OFF + off) = make_uint2(*(uint32_t*)&lA, *(uint32_t*)&lB);
        }
        if (tid < NCH) ns[tid] = g_norms[k0c + tid];
        __syncthreads();

        float hh[2][4][4], md[2][4][4];
        #pragma unroll
        for (int mt = 0; mt < 2; mt++)
            #pragma unroll
            for (int nb = 0; nb < 4; nb++)
                #pragma unroll
                for (int q = 0; q < 4; q++) { hh[mt][nb][q] = 0.f; md[mt][nb][q] = 0.f; }

        #pragma unroll 4
        for (int ks = 0; ks < KSTEPS; ks++) {
            uint32_t ah[2][4], al[2][4];
            #pragma unroll
            for (int mt = 0; mt < 2; mt++) {
                ldsm4(aH + (uint32_t)(mt * 16 * ROWB + ks * 32), ah[mt]);
                ldsm4(aL + (uint32_t)(mt * 16 * ROWB + ks * 32), al[mt]);
            }
            #pragma unroll
            for (int nb = 0; nb < 4; nb++) {
                uint32_t bh[2], bl[2];
                ldsm2(bHb + (uint32_t)(nb * 8 * ROWB + ks * 32), bh);
                ldsm2(bLb + (uint32_t)(nb * 8 * ROWB + ks * 32), bl);
                #pragma unroll
                for (int mt = 0; mt < 2; mt++) {
                    mma_f16(hh[mt][nb], ah[mt], bh[0], bh[1]);
                    mma_f16(md[mt][nb], ah[mt], bl[0], bl[1]);
                    mma_f16(md[mt][nb], al[mt], bh[0], bh[1]);
                }
            }
        }

        // epilogue: dist = |e|^2 - 2 (hh + mid/2048)
        #pragma unroll
        for (int nb = 0; nb < 4; nb++) {
            int cl = cg * 32 + nb * 8 + 2 * t;
            float nk0 = ns[cl];
            float nk1 = ns[cl + 1];
            int code0 = k0c + cl;
            #pragma unroll
            for (int mt = 0; mt < 2; mt++) {
                float d00 = nk0 - 2.f * (hh[mt][nb][0] + md[mt][nb][0] * LO_IS);
                float d01 = nk1 - 2.f * (hh[mt][nb][1] + md[mt][nb][1] * LO_IS);
                float d10 = nk0 - 2.f * (hh[mt][nb][2] + md[mt][nb][2] * LO_IS);
                float d11 = nk1 - 2.f * (hh[mt][nb][3] + md[mt][nb][3] * LO_IS);
                int s0 = mt * 2, s1 = mt * 2 + 1;
                if (d00 < bestv4[s0]) { bestv4[s0] = d00; besti4[s0] = code0; }
                if (d01 < bestv4[s0]) { bestv4[s0] = d01; besti4[s0] = code0 + 1; }
                if (d10 < bestv4[s1]) { bestv4[s1] = d10; besti4[s1] = code0; }
                if (d11 < bestv4[s1]) { bestv4[s1] = d11; besti4[s1] = code0 + 1; }
            }
        }
    }

    // lane-reduce across t (lanes 4g..4g+3 share a token row)
    #pragma unroll
    for (int s = 0; s < 4; s++) {
        #pragma unroll
        for (int m = 1; m <= 2; m <<= 1) {
            float v2 = __shfl_xor_sync(0xffffffffu, bestv4[s], m);
            int   i2 = __shfl_xor_sync(0xffffffffu, besti4[s], m);
            if (v2 < bestv4[s] || (v2 == bestv4[s] && i2 < besti4[s])) {
                bestv4[s] = v2; besti4[s] = i2;
            }
        }
    }
    if (t == 0) {
        #pragma unroll
        for (int s = 0; s < 4; s++) {
            int mt = s >> 1, h = s & 1;
            int tok = tg * 32 + mt * 16 + h * 8 + g;
            candv[tok * 2 + cg] = bestv4[s];
            candi[tok * 2 + cg] = besti4[s];
        }
    }
    __syncthreads();
    if (tid < MT) {
        float v0 = candv[tid * 2], v1 = candv[tid * 2 + 1];
        int   i0 = candi[tid * 2], i1 = candi[tid * 2 + 1];
        int bi;
        if (v1 < v0 || (v1 == v0 && i1 < i0)) bi = i1; else bi = i0;
        g_idx[n0 + tid] = bi;
        atomicAdd(&g_counts[bi], 1);
    }
}

// ---------------------------------------------------------------------------
// gather: 512 blocks, 64 tokens/block, 4 threads per token
__global__ __launch_bounds__(256)
void gather_loss_kernel(const float* __restrict__ z,
                        const float* __restrict__ cb,
                        float* __restrict__ out) {
    __shared__ float red[256];
    const int tid = threadIdx.x;
    const int tok = blockIdx.x * 64 + (tid & 63);
    const int cc  = tid >> 6;
    const int k   = g_idx[tok];
    const int b   = tok >> 10;
    const int hw  = tok & 1023;
    const float4* c4p = (const float4*)cb + (size_t)k * 64 + cc * 16;
    const size_t base = (size_t)b * (C_DIM * HW_DIM) + (size_t)cc * 64 * HW_DIM + hw;
    const float* zp = z + base;
    float* op = out + base;
    float s = 0.f;
    #pragma unroll
    for (int j = 0; j < 16; j++) {
        float4 e = c4p[j];
        int c = j * 4;
        float d0 = e.x - zp[(c + 0) * HW_DIM];
        float d1 = e.y - zp[(c + 1) * HW_DIM];
        float d2 = e.z - zp[(c + 2) * HW_DIM];
        float d3 = e.w - zp[(c + 3) * HW_DIM];
        s += d0 * d0 + d1 * d1 + d2 * d2 + d3 * d3;
        op[(c + 0) * HW_DIM] = e.x;
        op[(c + 1) * HW_DIM] = e.y;
        op[(c + 2) * HW_DIM] = e.z;
        op[(c + 3) * HW_DIM] = e.w;
    }
    red[tid] = s;
    __syncthreads();
    for (int off = 128; off > 0; off >>= 1) {
        if (tid < off) red[tid] += red[tid + off];
        __syncthreads();
    }
    if (tid == 0) g_partials[blockIdx.x] = red[0];
}

// ---------------------------------------------------------------------------
__global__ void finalize_kernel(float* __restrict__ out, int out_size) {
    __shared__ float s1[1024];
    __shared__ float s2[1024];
    const int tid = threadIdx.x;
    float ls = (tid < GL_BLOCKS) ? g_partials[tid] : 0.f;
    float p  = (float)g_counts[tid] * (1.0f / (float)N_TOK);
    float pc = fmaxf(p, 1e-10f);
    s1[tid] = ls;
    s2[tid] = pc * logf(pc);
    __syncthreads();
    for (int off = 512; off > 0; off >>= 1) {
        if (tid < off) { s1[tid] += s1[tid + off]; s2[tid] += s2[tid + off]; }
        __syncthreads();
    }
    if (tid == 0) {
        float mse = s1[0] * (1.0f / (float)Z_ELEMS);
        if (out_size >= Z_ELEMS + 1) out[Z_ELEMS]     = mse * (1.0f + BETA_F);
        if (out_size >= Z_ELEMS + 2) out[Z_ELEMS + 1] = expf(-s2[0]);
    }
}

// ---------------------------------------------------------------------------
extern "C" void kernel_launch(void* const* d_in, const int* in_sizes, int n_in,
                              void* d_out, int out_size) {
    const float* z  = (const float*)d_in[0];
    const float* cb = (const float*)d_in[1];
    float* out = (float*)d_out;

    cudaFuncSetAttribute(argmin_kernel,
                         cudaFuncAttributeMaxDynamicSharedMemorySize, SMEM_TOTAL);

    init_kernel<<<1, K_CODES>>>();
    norms_kernel<<<K_CODES / 8, 256>>>(cb);
    argmin_kernel<<<N_TOK / MT, 256, SMEM_TOTAL>>>(z, cb);
    gather_loss_kernel<<<GL_BLOCKS, 256>>>(z, cb, out);
    finalize_kernel<<<1, 1024>>>(out, out_size);
}